// round 1
// baseline (speedup 1.0000x reference)
#include <cuda_runtime.h>
#include <math.h>

#define N_NODES 100000
#define N_EDGES 3200000
#define HID 25
#define HPAD 32
#define NH 5
#define MH 50
#define MHP 52   // padded hidden width (16B-aligned rows)

// ---------------- static device scratch (no runtime allocation) ----------------
__device__ float  g_xt [N_NODES * 8];      // [x, token0..4, 0, 0]
__device__ float  g_hn [N_NODES * HPAD];   // node state (25 used)
__device__ float  g_q  [N_NODES * HPAD];
__device__ float  g_k  [N_NODES * HPAD];
__device__ float  g_v  [N_NODES * HPAD];
__device__ float  g_sk [N_NODES * HPAD];
__device__ int    g_deg[N_NODES];
__device__ int    g_off[N_NODES + 1];
__device__ int    g_cur[N_NODES];
__device__ float4 g_pay[N_EDGES];          // {src_bits, edge_attr, edge_value, 0}

__device__ __forceinline__ float gelu_f(float x) {
    return 0.5f * x * (1.0f + erff(x * 0.70710678118654752440f));
}

// ---------------- kernels ----------------
__global__ void k_zero() {
    int i = blockIdx.x * blockDim.x + threadIdx.x;
    if (i < N_NODES) g_deg[i] = 0;
}

__global__ void k_node_init(const float* __restrict__ x, const float* __restrict__ token,
                            const float* __restrict__ ilW, const float* __restrict__ ilb) {
    __shared__ float sW[6 * 28];
    __shared__ float sb[28];
    for (int t = threadIdx.x; t < 6 * 28; t += blockDim.x) {
        int i = t / 28, j = t % 28;
        sW[t] = (j < HID) ? ilW[i * HID + j] : 0.f;
    }
    for (int t = threadIdx.x; t < 28; t += blockDim.x) sb[t] = (t < HID) ? ilb[t] : 0.f;
    __syncthreads();
    int n = blockIdx.x * blockDim.x + threadIdx.x;
    if (n >= N_NODES) return;
    float xt[6];
    xt[0] = x[n];
#pragma unroll
    for (int i = 0; i < 5; i++) xt[1 + i] = token[n * 5 + i];
    float4* xo = (float4*)(g_xt + (size_t)n * 8);
    xo[0] = make_float4(xt[0], xt[1], xt[2], xt[3]);
    xo[1] = make_float4(xt[4], xt[5], 0.f, 0.f);
    float acc[28];
#pragma unroll
    for (int j = 0; j < 28; j++) acc[j] = sb[j];
#pragma unroll
    for (int i = 0; i < 6; i++) {
        float xi = xt[i];
#pragma unroll
        for (int j = 0; j < 28; j++) acc[j] += xi * sW[i * 28 + j];
    }
    float4* ho = (float4*)(g_hn + (size_t)n * HPAD);
#pragma unroll
    for (int j4 = 0; j4 < 7; j4++)
        ho[j4] = make_float4(acc[j4 * 4], acc[j4 * 4 + 1], acc[j4 * 4 + 2], acc[j4 * 4 + 3]);
    ho[7] = make_float4(0.f, 0.f, 0.f, 0.f);
}

__global__ void k_count(const int* __restrict__ ei) {
    int e = blockIdx.x * blockDim.x + threadIdx.x;
    if (e < N_EDGES) atomicAdd(&g_deg[ei[N_EDGES + e]], 1);
}

__global__ void k_scan() {   // single block, 1024 threads
    __shared__ int s[1024];
    int carry = 0;
    for (int base = 0; base < N_NODES; base += 1024) {
        int i = base + threadIdx.x;
        int v = (i < N_NODES) ? g_deg[i] : 0;
        s[threadIdx.x] = v;
        __syncthreads();
        for (int st = 1; st < 1024; st <<= 1) {
            int t = (threadIdx.x >= st) ? s[threadIdx.x - st] : 0;
            __syncthreads();
            s[threadIdx.x] += t;
            __syncthreads();
        }
        if (i < N_NODES) {
            int incl = s[threadIdx.x];
            g_off[i + 1] = carry + incl;
            g_cur[i]     = carry + incl - v;
        }
        carry += s[1023];
        __syncthreads();
    }
    if (threadIdx.x == 0) g_off[0] = 0;
}

// Edge MLP (13->50->50->50->2) + straight-through argmax + CSR payload scatter
__global__ __launch_bounds__(256) void k_mlp(
    const float* __restrict__ W0, const float* __restrict__ b0,
    const float* __restrict__ W1, const float* __restrict__ b1,
    const float* __restrict__ W2, const float* __restrict__ b2,
    const float* __restrict__ W3, const float* __restrict__ b3,
    const float* __restrict__ ea_arr, const float* __restrict__ gum,
    const int* __restrict__ ei)
{
    __shared__ float sW0[13 * MHP], sb0[MHP];
    __shared__ float sW1[MHP * MHP], sb1[MHP];
    __shared__ float sW2[MHP * MHP], sb2[MHP];
    __shared__ float sW3a[MHP], sW3b[MHP], sb3[2];

    for (int t = threadIdx.x; t < 13 * MHP; t += blockDim.x) {
        int i = t / MHP, j = t % MHP;
        sW0[t] = (j < MH) ? W0[i * MH + j] : 0.f;
    }
    for (int t = threadIdx.x; t < MHP * MHP; t += blockDim.x) {
        int i = t / MHP, j = t % MHP;
        float w1 = 0.f, w2 = 0.f;
        if (i < MH && j < MH) { w1 = W1[i * MH + j]; w2 = W2[i * MH + j]; }
        sW1[t] = w1; sW2[t] = w2;
    }
    for (int t = threadIdx.x; t < MHP; t += blockDim.x) {
        sb0[t]  = (t < MH) ? b0[t] : 0.f;
        sb1[t]  = (t < MH) ? b1[t] : 0.f;
        sb2[t]  = (t < MH) ? b2[t] : 0.f;
        sW3a[t] = (t < MH) ? W3[t * 2 + 0] : 0.f;
        sW3b[t] = (t < MH) ? W3[t * 2 + 1] : 0.f;
    }
    if (threadIdx.x < 2) sb3[threadIdx.x] = b3[threadIdx.x];
    __syncthreads();

    int e = blockIdx.x * blockDim.x + threadIdx.x;
    if (e >= N_EDGES) return;
    int src = ei[e], dst = ei[N_EDGES + e];
    float ea = ea_arr[e];

    float4 xs0 = *(const float4*)(g_xt + (size_t)src * 8);
    float4 xs1 = *(const float4*)(g_xt + (size_t)src * 8 + 4);
    float4 xd0 = *(const float4*)(g_xt + (size_t)dst * 8);
    float4 xd1 = *(const float4*)(g_xt + (size_t)dst * 8 + 4);
    float in13[13] = { xs0.x, xs0.y, xs0.z, xs0.w, xs1.x, xs1.y,
                       xd0.x, xd0.y, xd0.z, xd0.w, xd1.x, xd1.y, ea };

    float a[MHP], h[MH];
#pragma unroll
    for (int j = 0; j < MHP; j++) a[j] = sb0[j];
#pragma unroll
    for (int i = 0; i < 13; i++) {
        float xi = in13[i];
        const float4* w = (const float4*)(sW0 + i * MHP);
#pragma unroll
        for (int j4 = 0; j4 < 13; j4++) {
            float4 w4 = w[j4];
            a[j4 * 4 + 0] += xi * w4.x; a[j4 * 4 + 1] += xi * w4.y;
            a[j4 * 4 + 2] += xi * w4.z; a[j4 * 4 + 3] += xi * w4.w;
        }
    }
#pragma unroll
    for (int j = 0; j < MH; j++) h[j] = gelu_f(a[j]);

#pragma unroll
    for (int j = 0; j < MHP; j++) a[j] = sb1[j];
#pragma unroll 2
    for (int i = 0; i < MH; i++) {
        float xi = h[i];
        const float4* w = (const float4*)(sW1 + i * MHP);
#pragma unroll
        for (int j4 = 0; j4 < 13; j4++) {
            float4 w4 = w[j4];
            a[j4 * 4 + 0] += xi * w4.x; a[j4 * 4 + 1] += xi * w4.y;
            a[j4 * 4 + 2] += xi * w4.z; a[j4 * 4 + 3] += xi * w4.w;
        }
    }
#pragma unroll
    for (int j = 0; j < MH; j++) h[j] = gelu_f(a[j]);

#pragma unroll
    for (int j = 0; j < MHP; j++) a[j] = sb2[j];
#pragma unroll 2
    for (int i = 0; i < MH; i++) {
        float xi = h[i];
        const float4* w = (const float4*)(sW2 + i * MHP);
#pragma unroll
        for (int j4 = 0; j4 < 13; j4++) {
            float4 w4 = w[j4];
            a[j4 * 4 + 0] += xi * w4.x; a[j4 * 4 + 1] += xi * w4.y;
            a[j4 * 4 + 2] += xi * w4.z; a[j4 * 4 + 3] += xi * w4.w;
        }
    }
#pragma unroll
    for (int j = 0; j < MH; j++) h[j] = gelu_f(a[j]);

    float l0 = sb3[0], l1 = sb3[1];
#pragma unroll 2
    for (int i = 0; i < MH; i++) { l0 += h[i] * sW3a[i]; l1 += h[i] * sW3b[i]; }

    // forward value of straight-through gumbel softmax = one-hot argmax
    float ev = (l1 + gum[2 * e + 1] > l0 + gum[2 * e]) ? 1.f : 0.f;

    int pos = atomicAdd(&g_cur[dst], 1);
    g_pay[pos] = make_float4(__int_as_float(src), ea, ev, 0.f);
}

// per-layer node transforms: q, k, v, skip
__global__ __launch_bounds__(128) void k_qkv(
    const float* __restrict__ Wq, const float* __restrict__ bq,
    const float* __restrict__ Wk, const float* __restrict__ bk,
    const float* __restrict__ Wv, const float* __restrict__ bv,
    const float* __restrict__ Ws, const float* __restrict__ bs, int l)
{
    __shared__ float sW[4][25 * 28];
    __shared__ float sb[4][28];
    const float* Wl[4] = { Wq + l * 625, Wk + l * 625, Wv + l * 625, Ws + l * 625 };
    const float* bl[4] = { bq + l * 25,  bk + l * 25,  bv + l * 25,  bs + l * 25 };
    for (int m = 0; m < 4; m++) {
        for (int t = threadIdx.x; t < 25 * 28; t += blockDim.x) {
            int i = t / 28, j = t % 28;
            sW[m][t] = (j < 25) ? Wl[m][i * 25 + j] : 0.f;
        }
        for (int t = threadIdx.x; t < 28; t += blockDim.x)
            sb[m][t] = (t < 25) ? bl[m][t] : 0.f;
    }
    __syncthreads();
    int n = blockIdx.x * blockDim.x + threadIdx.x;
    if (n >= N_NODES) return;
    float hv[25];
#pragma unroll
    for (int c = 0; c < 25; c++) hv[c] = g_hn[(size_t)n * HPAD + c];
    float* outs[4] = { g_q + (size_t)n * HPAD, g_k + (size_t)n * HPAD,
                       g_v + (size_t)n * HPAD, g_sk + (size_t)n * HPAD };
#pragma unroll
    for (int m = 0; m < 4; m++) {
        float acc[28];
#pragma unroll
        for (int j = 0; j < 28; j++) acc[j] = sb[m][j];
#pragma unroll 5
        for (int i = 0; i < 25; i++) {
            float xi = hv[i];
            const float4* w = (const float4*)(&sW[m][i * 28]);
#pragma unroll
            for (int j4 = 0; j4 < 7; j4++) {
                float4 w4 = w[j4];
                acc[j4 * 4 + 0] += xi * w4.x; acc[j4 * 4 + 1] += xi * w4.y;
                acc[j4 * 4 + 2] += xi * w4.z; acc[j4 * 4 + 3] += xi * w4.w;
            }
        }
        float4* o = (float4*)outs[m];
#pragma unroll
        for (int j4 = 0; j4 < 7; j4++)
            o[j4] = make_float4(acc[j4 * 4], acc[j4 * 4 + 1], acc[j4 * 4 + 2], acc[j4 * 4 + 3]);
    }
}

// one warp per node; lane-per-edge; online softmax with per-lane partials
__global__ __launch_bounds__(256) void k_attn(const float* __restrict__ We,
                                              const float* __restrict__ be_, int l)
{
    __shared__ float sWe0[28], sWe1[28], sbe[28];
    if (threadIdx.x < 28) {
        int c = threadIdx.x;
        sWe0[c] = (c < 25) ? We[l * 50 + c]      : 0.f;
        sWe1[c] = (c < 25) ? We[l * 50 + 25 + c] : 0.f;
        sbe[c]  = (c < 25) ? be_[l * 25 + c]     : 0.f;
    }
    __syncthreads();
    int warp = threadIdx.x >> 5, lane = threadIdx.x & 31;
    int n = blockIdx.x * 8 + warp;
    if (n >= N_NODES) return;

    int beg = g_off[n], end = g_off[n + 1];
    float q[28];
    {
        const float4* qr = (const float4*)(g_q + (size_t)n * HPAD);
#pragma unroll
        for (int c4 = 0; c4 < 7; c4++) {
            float4 t = qr[c4];
            q[c4 * 4] = t.x; q[c4 * 4 + 1] = t.y; q[c4 * 4 + 2] = t.z; q[c4 * 4 + 3] = t.w;
        }
    }
    float acc[25], m[NH], d[NH];
#pragma unroll
    for (int c = 0; c < 25; c++) acc[c] = 0.f;
#pragma unroll
    for (int hh = 0; hh < NH; hh++) { m[hh] = -1e30f; d[hh] = 0.f; }
    const float scale = 0.44721359549995794f;  // 1/sqrt(5)

    for (int base = beg; base < end; base += 32) {
        int idx = base + lane;
        bool act = idx < end;
        float e[25];
        float al[NH] = {0.f, 0.f, 0.f, 0.f, 0.f};
        int src = 0;
        if (act) {
            float4 p = g_pay[idx];
            src = __float_as_int(p.x);
            float eav = p.y, evv = p.z;
            const float4* kr = (const float4*)(g_k + (size_t)src * HPAD);
            float kk[28];
#pragma unroll
            for (int c4 = 0; c4 < 7; c4++) {
                float4 t = kr[c4];
                kk[c4 * 4] = t.x; kk[c4 * 4 + 1] = t.y; kk[c4 * 4 + 2] = t.z; kk[c4 * 4 + 3] = t.w;
            }
#pragma unroll
            for (int c = 0; c < 25; c++) {
                float ee = sbe[c] + eav * sWe0[c] + evv * sWe1[c];
                e[c] = ee;
                al[c / 5] += q[c] * (kk[c] + ee);
            }
        }
        float am[NH];
#pragma unroll
        for (int hh = 0; hh < NH; hh++) {
            am[hh] = act ? al[hh] * scale : -1e30f;
#pragma unroll
            for (int off = 16; off >= 1; off >>= 1)
                am[hh] = fmaxf(am[hh], __shfl_xor_sync(0xffffffffu, am[hh], off));
        }
        float corr[NH];
#pragma unroll
        for (int hh = 0; hh < NH; hh++) {
            float nm = fmaxf(m[hh], am[hh]);
            corr[hh] = __expf(m[hh] - nm);
            m[hh] = nm;
            d[hh] *= corr[hh];
        }
#pragma unroll
        for (int c = 0; c < 25; c++) acc[c] *= corr[c / 5];
        if (act) {
            float ex[NH];
#pragma unroll
            for (int hh = 0; hh < NH; hh++) {
                ex[hh] = __expf(al[hh] * scale - m[hh]);
                d[hh] += ex[hh];
            }
            const float4* vr = (const float4*)(g_v + (size_t)src * HPAD);
            float vv[28];
#pragma unroll
            for (int c4 = 0; c4 < 7; c4++) {
                float4 t = vr[c4];
                vv[c4 * 4] = t.x; vv[c4 * 4 + 1] = t.y; vv[c4 * 4 + 2] = t.z; vv[c4 * 4 + 3] = t.w;
            }
#pragma unroll
            for (int c = 0; c < 25; c++) acc[c] += ex[c / 5] * (vv[c] + e[c]);
        }
    }
    // cross-lane reduction of partials
#pragma unroll
    for (int hh = 0; hh < NH; hh++)
#pragma unroll
        for (int off = 16; off >= 1; off >>= 1)
            d[hh] += __shfl_xor_sync(0xffffffffu, d[hh], off);
#pragma unroll
    for (int c = 0; c < 25; c++)
#pragma unroll
        for (int off = 16; off >= 1; off >>= 1)
            acc[c] += __shfl_xor_sync(0xffffffffu, acc[c], off);
    if (lane == 0) {
#pragma unroll
        for (int c = 0; c < 25; c++)
            g_hn[(size_t)n * HPAD + c] =
                acc[c] / (d[c / 5] + 1e-16f) + g_sk[(size_t)n * HPAD + c];
    }
}

__global__ void k_out(const float* __restrict__ oW, const float* __restrict__ ob,
                      float* __restrict__ out) {
    __shared__ float sw[25];
    __shared__ float sb0;
    if (threadIdx.x < 25) sw[threadIdx.x] = oW[threadIdx.x];
    if (threadIdx.x == 0) sb0 = ob[0];
    __syncthreads();
    int n = blockIdx.x * blockDim.x + threadIdx.x;
    if (n >= N_NODES) return;
    float z = sb0;
#pragma unroll
    for (int c = 0; c < 25; c++) z += g_hn[(size_t)n * HPAD + c] * sw[c];
    out[n] = 1.f / (1.f + __expf(-z));
}

// ---------------- launcher ----------------
extern "C" void kernel_launch(void* const* d_in, const int* in_sizes, int n_in,
                              void* d_out, int out_size) {
    const float* x     = (const float*)d_in[0];
    const float* token = (const float*)d_in[1];
    const float* ea    = (const float*)d_in[2];
    const float* gum   = (const float*)d_in[3];
    const int* ei;
    int pb;
    if (in_sizes[4] == 2 * N_EDGES) {        // setup_inputs dict order: edge_index at idx 4
        ei = (const int*)d_in[4];
        pb = 5;
    } else {                                  // signature order: edge_index last
        ei = (const int*)d_in[n_in - 1];
        pb = 4;
    }
    const float* W0  = (const float*)d_in[pb + 0];
    const float* b0  = (const float*)d_in[pb + 1];
    const float* W1  = (const float*)d_in[pb + 2];
    const float* b1  = (const float*)d_in[pb + 3];
    const float* W2  = (const float*)d_in[pb + 4];
    const float* b2  = (const float*)d_in[pb + 5];
    const float* W3  = (const float*)d_in[pb + 6];
    const float* b3  = (const float*)d_in[pb + 7];
    const float* ilW = (const float*)d_in[pb + 8];
    const float* ilb = (const float*)d_in[pb + 9];
    const float* Wq  = (const float*)d_in[pb + 10];
    const float* bq  = (const float*)d_in[pb + 11];
    const float* Wk  = (const float*)d_in[pb + 12];
    const float* bk  = (const float*)d_in[pb + 13];
    const float* Wv  = (const float*)d_in[pb + 14];
    const float* bv  = (const float*)d_in[pb + 15];
    const float* We  = (const float*)d_in[pb + 16];
    const float* be  = (const float*)d_in[pb + 17];
    const float* Wsk = (const float*)d_in[pb + 18];
    const float* bsk = (const float*)d_in[pb + 19];
    const float* oW  = (const float*)d_in[pb + 20];
    const float* ob  = (const float*)d_in[pb + 21];

    int nb = (N_NODES + 255) / 256;
    int eb = (N_EDGES + 255) / 256;

    k_zero<<<nb, 256>>>();
    k_node_init<<<nb, 256>>>(x, token, ilW, ilb);
    k_count<<<eb, 256>>>(ei);
    k_scan<<<1, 1024>>>();
    k_mlp<<<eb, 256>>>(W0, b0, W1, b1, W2, b2, W3, b3, ea, gum, ei);
    for (int l = 0; l < 3; l++) {
        k_qkv<<<(N_NODES + 127) / 128, 128>>>(Wq, bq, Wk, bk, Wv, bv, Wsk, bsk, l);
        k_attn<<<(N_NODES + 7) / 8, 256>>>(We, be, l);
    }
    k_out<<<nb, 256>>>(oW, ob, (float*)d_out);
}